// round 9
// baseline (speedup 1.0000x reference)
#include <cuda_runtime.h>
#include <math.h>
#include <stdint.h>

// ---------------------------------------------------------------------------
// KAN layer as one concatenated INT8 GEMM (mma.sync m16n8k32 s8, s32 acc).
//   out[b,o] = sum_i w[i,o]*silu(x[b,i]) + sum_{i,k} bx[b,i,k]*(w[i,o]*c[i,o,k])
// silu s = S_a (a_hi + a_lo/128), w = S_b (b_hi + b_lo/128)  (s8 two-level)
// K layout (KTOT=7680):
//   [0   , 512): A=a_lo B=b_lo   (unit S1/2^14)      \  z0, Horner shifts
//   [512 ,1024): A=a_lo B=b_hi   (unit S1/2^7)        | acc>>7 at k=512? no:
//   [1024,1536): A=a_hi B=b_lo   (unit S1/2^7)        | shift after 512 and
//   [1536,2048): A=a_hi B=b_hi   (unit S1)           /  after 1536
//   [2048,7680): k=2048+kk*512+i : A=q(basis) B=q(w*c), unit S_sp
// z-splits: z0=[0,2048) 16 iters; z1..3 spline 15/15/14 iters. Per-z scale
// applied when writing f32 partials; deterministic fused finalize.
// ---------------------------------------------------------------------------

#define BATCH 1024
#define NIN   512
#define NOUT  512
#define NB    11
#define KSIL  2048
#define KTOT  7680

#define BM 128
#define BN 128
#define BK 128            // 128 s8 = 128 B rows
#define SPLITK 4
#define STAGES 3
#define ASTAGE (BM * BK)  // 16384 B
#define BSTAGE (BN * BK)  // 16384 B
#define STAGE_BYTES (ASTAGE + BSTAGE)       // 32768
#define SMEM_TOTAL (STAGES * STAGE_BYTES)   // 98304

// quantization scales
#define SA      (5.8f / 127.0f)
#define SB      (0.26f / 127.0f)
#define INV_SA  (127.0f / 5.8f)
#define INV_SB  (127.0f / 0.26f)
#define INV_SBAS 190.5f                      // 127 / (2/3)
#define INV_SWC (127.0f / 1.6e-3f)
#define SC_SIL  ((5.8f * 0.26f) / (127.0f * 127.0f))
#define SC_SPL  (((2.0f / 3.0f) * 1.6e-3f) / (127.0f * 127.0f))

// Scratch (allocation-free rule: __device__ globals)
__device__ __align__(128) char  g_A8 [(size_t)BATCH * KTOT];
__device__ __align__(128) char  g_B8 [(size_t)NOUT  * KTOT];
__device__ __align__(128) float g_P  [(size_t)SPLITK * BATCH * NOUT];
__device__ int g_cnt[(BATCH / BM) * (NOUT / BN)];

// ---------------------------------------------------------------------------
// Cubic B-spline basis (Cox-de Boor). knots t_m = -5.25 + 0.75*m (exact fp32)
// ---------------------------------------------------------------------------
__device__ __forceinline__ void basis11(float x, float* Bv /*[14]*/) {
#pragma unroll
    for (int m = 0; m < 14; m++) {
        float tl = -5.25f + 0.75f * (float)m;
        Bv[m] = (x >= tl && x < tl + 0.75f) ? 1.0f : 0.0f;
    }
#pragma unroll
    for (int d = 1; d <= 3; d++) {
        float inv = 1.0f / (0.75f * (float)d);
#pragma unroll
        for (int m = 0; m < 13; m++) {
            if (m < 14 - d) {
                float tm    = -5.25f + 0.75f * (float)m;
                float left  = (x - tm) * inv;
                float right = ((tm + 0.75f * (float)(d + 1)) - x) * inv;
                Bv[m] = left * Bv[m] + right * Bv[m + 1];
            }
        }
    }
}

__device__ __forceinline__ int clamp127(int v) {
    return v < -127 ? -127 : (v > 127 ? 127 : v);
}

// ---------------------------------------------------------------------------
// prep_a8: thread handles 4 consecutive i of one batch row (char4 stores)
// ---------------------------------------------------------------------------
__global__ void __launch_bounds__(256) prep_a8(const float* __restrict__ X) {
    int pid = blockIdx.x * 256 + threadIdx.x;   // 131072
    int b  = pid >> 7;
    int ig = pid & 127;
    float4 xv = *(const float4*)(X + (size_t)b * NIN + ig * 4);
    float x[4] = {xv.x, xv.y, xv.z, xv.w};

    char hi[4], lo[4];
#pragma unroll
    for (int j = 0; j < 4; j++) {
        float s = x[j] / (1.0f + __expf(-x[j]));
        float t = s * INV_SA;
        int h = __float2int_rn(t);
        h = clamp127(h);
        int l = __float2int_rn((t - (float)h) * 128.0f);
        l = clamp127(l);
        hi[j] = (char)h;
        lo[j] = (char)l;
    }
    char* row = g_A8 + (size_t)b * KTOT;
    *(char4*)(row + ig * 4)        = make_char4(lo[0], lo[1], lo[2], lo[3]);
    *(char4*)(row + 512 + ig * 4)  = make_char4(lo[0], lo[1], lo[2], lo[3]);
    *(char4*)(row + 1024 + ig * 4) = make_char4(hi[0], hi[1], hi[2], hi[3]);
    *(char4*)(row + 1536 + ig * 4) = make_char4(hi[0], hi[1], hi[2], hi[3]);

    float B0[14], B1[14], B2[14], B3[14];
    basis11(x[0], B0);
    basis11(x[1], B1);
    basis11(x[2], B2);
    basis11(x[3], B3);
#pragma unroll
    for (int kk = 0; kk < NB; kk++) {
        char q0 = (char)__float2int_rn(B0[kk] * INV_SBAS);
        char q1 = (char)__float2int_rn(B1[kk] * INV_SBAS);
        char q2 = (char)__float2int_rn(B2[kk] * INV_SBAS);
        char q3 = (char)__float2int_rn(B3[kk] * INV_SBAS);
        *(char4*)(row + KSIL + kk * NIN + ig * 4) = make_char4(q0, q1, q2, q3);
    }
}

// ---------------------------------------------------------------------------
// prep_b8: thread handles 4 consecutive i for one o
// ---------------------------------------------------------------------------
__global__ void __launch_bounds__(256) prep_b8(const float* __restrict__ W,
                                               const float* __restrict__ C) {
    int pid = blockIdx.x * 256 + threadIdx.x;   // 65536
    int o  = pid >> 7;
    int ig = pid & 127;

    float w[4];
    char hi[4], lo[4];
#pragma unroll
    for (int j = 0; j < 4; j++) {
        w[j] = W[(size_t)(ig * 4 + j) * NOUT + o];
        float t = w[j] * INV_SB;
        int h = __float2int_rn(t);
        h = clamp127(h);
        int l = __float2int_rn((t - (float)h) * 128.0f);
        l = clamp127(l);
        hi[j] = (char)h;
        lo[j] = (char)l;
    }
    char* row = g_B8 + (size_t)o * KTOT;
    *(char4*)(row + ig * 4)        = make_char4(lo[0], lo[1], lo[2], lo[3]);
    *(char4*)(row + 512 + ig * 4)  = make_char4(hi[0], hi[1], hi[2], hi[3]);
    *(char4*)(row + 1024 + ig * 4) = make_char4(lo[0], lo[1], lo[2], lo[3]);
    *(char4*)(row + 1536 + ig * 4) = make_char4(hi[0], hi[1], hi[2], hi[3]);

#pragma unroll
    for (int kk = 0; kk < NB; kk++) {
        char q[4];
#pragma unroll
        for (int j = 0; j < 4; j++) {
            float wc = w[j] * C[((size_t)(ig * 4 + j) * NOUT + o) * NB + kk];
            q[j] = (char)clamp127(__float2int_rn(wc * INV_SWC));
        }
        *(char4*)(row + KSIL + kk * NIN + ig * 4) = make_char4(q[0], q[1], q[2], q[3]);
    }
}

// ---------------------------------------------------------------------------
// GEMM helpers
// ---------------------------------------------------------------------------
__device__ __forceinline__ void cpa16(uint32_t dst, const void* src) {
    asm volatile("cp.async.cg.shared.global [%0], [%1], 16;\n" :: "r"(dst), "l"(src));
}

#define LDSM_X4(r, addr)                                                       \
    asm volatile("ldmatrix.sync.aligned.m8n8.x4.shared.b16 {%0,%1,%2,%3}, [%4];\n" \
                 : "=r"((r)[0]), "=r"((r)[1]), "=r"((r)[2]), "=r"((r)[3])      \
                 : "r"(addr))

#define MMA16832(d, a, b0_, b1_)                                               \
    asm volatile("mma.sync.aligned.m16n8k32.row.col.s32.s8.s8.s32 "            \
                 "{%0,%1,%2,%3}, {%4,%5,%6,%7}, {%8,%9}, {%0,%1,%2,%3};\n"     \
                 : "+r"((d)[0]), "+r"((d)[1]), "+r"((d)[2]), "+r"((d)[3])      \
                 : "r"((a)[0]), "r"((a)[1]), "r"((a)[2]), "r"((a)[3]),         \
                   "r"(b0_), "r"(b1_))

// stage: A 128 rows x 128B (SW: chunk c ^ (r&7)), B 128 rows x 128B
__device__ __forceinline__ void load_stage(const char* Ag, const char* Bg, int kt,
                                           int tid, uint32_t smem_u32) {
    uint32_t base = smem_u32 + (kt % STAGES) * STAGE_BYTES;
    const char* Ak = Ag + (size_t)kt * BK;
#pragma unroll
    for (int it = 0; it < 4; it++) {
        int t = tid + it * 256;
        int r = t >> 3, c = t & 7;
        uint32_t dst = base + r * 128 + ((c ^ (r & 7)) << 4);
        cpa16(dst, Ak + (size_t)r * KTOT + (c << 4));
    }
    const char* Bk = Bg + (size_t)kt * BK;
#pragma unroll
    for (int it = 0; it < 4; it++) {
        int t = tid + it * 256;
        int r = t >> 3, c = t & 7;
        uint32_t dst = base + ASTAGE + r * 128 + ((c ^ (r & 7)) << 4);
        cpa16(dst, Bk + (size_t)r * KTOT + (c << 4));
    }
    asm volatile("cp.async.commit_group;\n" ::);
}

__global__ void __launch_bounds__(256, 1) kan_gemm_i8(float* __restrict__ Out) {
    extern __shared__ __align__(1024) char smem[];
    __shared__ int s_last;

    const uint32_t smem_u32 = (uint32_t)__cvta_generic_to_shared(smem);
    const int tid  = threadIdx.x;
    const int m0   = blockIdx.x * BM;
    const int n0   = blockIdx.y * BN;
    const int z    = blockIdx.z;

    // z-split: z0 = silu [0,2048) 16 iters; z1..3 spline 15/15/14 iters
    const int k0 = (z == 0) ? 0 : 2048 + (z - 1) * 1920;   // z3: 5888
    const int ni = (z == 0) ? 16 : ((z == 3) ? 14 : 15);

    const char* Ag = g_A8 + (size_t)m0 * KTOT + k0;
    const char* Bg = g_B8 + (size_t)n0 * KTOT + k0;

    const int lane = tid & 31;
    const int warp = tid >> 5;
    const int wm   = warp >> 1;   // 0..3 : 32-row band
    const int wn   = warp & 1;    // 0..1 : 64-col band
    const int lr   = lane & 15;
    const int hf   = lane >> 4;

    int acc[2][8][4];
#pragma unroll
    for (int mt = 0; mt < 2; mt++)
#pragma unroll
        for (int nt = 0; nt < 8; nt++)
#pragma unroll
            for (int e = 0; e < 4; e++) acc[mt][nt][e] = 0;

    load_stage(Ag, Bg, 0, tid, smem_u32);
    load_stage(Ag, Bg, 1, tid, smem_u32);
    load_stage(Ag, Bg, 2, tid, smem_u32);

    for (int kt = 0; kt < ni; kt++) {
        asm volatile("cp.async.wait_group 2;\n" ::);   // stage kt resident (own)
        __syncthreads();                               // all threads' copies visible

        // Horner scale shifts for z0: after lo*lo (k<512) and after mixed (k<1536)
        if (z == 0 && (kt == 4 || kt == 12)) {
#pragma unroll
            for (int mt = 0; mt < 2; mt++)
#pragma unroll
                for (int nt = 0; nt < 8; nt++)
#pragma unroll
                    for (int e = 0; e < 4; e++)
                        acc[mt][nt][e] = (acc[mt][nt][e] + 64) >> 7;
        }

        const uint32_t sbase = smem_u32 + (kt % STAGES) * STAGE_BYTES;

#pragma unroll
        for (int ks = 0; ks < 4; ks++) {               // 4 k32-steps per 128-K iter
            uint32_t af[2][4], bf[4][4];
#pragma unroll
            for (int mt = 0; mt < 2; mt++) {
                int r  = wm * 32 + mt * 16 + lr;
                int ch = (ks * 2 + hf) ^ (r & 7);
                LDSM_X4(af[mt], sbase + r * 128 + (ch << 4));
            }
#pragma unroll
            for (int p = 0; p < 4; p++) {
                int r  = wn * 64 + p * 16 + lr;
                int ch = (ks * 2 + hf) ^ (r & 7);
                LDSM_X4(bf[p], sbase + ASTAGE + r * 128 + (ch << 4));
            }
#pragma unroll
            for (int mt = 0; mt < 2; mt++)
#pragma unroll
                for (int p = 0; p < 4; p++)
#pragma unroll
                    for (int q = 0; q < 2; q++)
                        MMA16832(acc[mt][p * 2 + q], af[mt], bf[p][q], bf[p][q + 2]);
        }
        __syncthreads();                               // readers done with slot

        if (kt + 3 < ni)
            load_stage(Ag, Bg, kt + 3, tid, smem_u32);
        else
            asm volatile("cp.async.commit_group;\n" ::);
    }

    // write scaled f32 split-K partial
    const float sc = (z == 0) ? SC_SIL : SC_SPL;
    float* P = g_P + (size_t)z * BATCH * NOUT;
#pragma unroll
    for (int mt = 0; mt < 2; mt++)
#pragma unroll
        for (int nt = 0; nt < 8; nt++) {
            int row0 = m0 + wm * 32 + mt * 16 + (lane >> 2);
            int col  = n0 + wn * 64 + nt * 8 + (lane & 3) * 2;
            *(float2*)&P[(size_t)row0 * NOUT + col] =
                make_float2(sc * (float)acc[mt][nt][0], sc * (float)acc[mt][nt][1]);
            *(float2*)&P[(size_t)(row0 + 8) * NOUT + col] =
                make_float2(sc * (float)acc[mt][nt][2], sc * (float)acc[mt][nt][3]);
        }
    __threadfence();
    __syncthreads();

    // deterministic fixed-order finalization by last-arriving z for this tile
    const int tile = blockIdx.x * (NOUT / BN) + blockIdx.y;
    if (tid == 0) s_last = (atomicAdd(&g_cnt[tile], 1) == SPLITK - 1) ? 1 : 0;
    __syncthreads();
    if (s_last) {
        __threadfence();
#pragma unroll
        for (int it = 0; it < 16; it++) {
            int t   = tid + it * 256;
            int row = m0 + (t >> 5);
            int c4  = (t & 31);
            size_t off = ((size_t)row * NOUT + n0) / 4 + c4;
            const float4* P0 = (const float4*)g_P + 0 * (size_t)(BATCH * NOUT / 4) + off;
            const float4* P1 = (const float4*)g_P + 1 * (size_t)(BATCH * NOUT / 4) + off;
            const float4* P2 = (const float4*)g_P + 2 * (size_t)(BATCH * NOUT / 4) + off;
            const float4* P3 = (const float4*)g_P + 3 * (size_t)(BATCH * NOUT / 4) + off;
            float4 a = *P0, b = *P1, c = *P2, e = *P3;
            float4 r;
            r.x = (a.x + b.x) + (c.x + e.x);
            r.y = (a.y + b.y) + (c.y + e.y);
            r.z = (a.z + b.z) + (c.z + e.z);
            r.w = (a.w + b.w) + (c.w + e.w);
            ((float4*)Out)[off] = r;
        }
        if (tid == 0) g_cnt[tile] = 0;   // rearm for graph replay
    }
}

// ---------------------------------------------------------------------------
extern "C" void kernel_launch(void* const* d_in, const int* in_sizes, int n_in,
                              void* d_out, int out_size) {
    const float* X = nullptr;
    const float* C = nullptr;
    const float* W = nullptr;
    for (int i = 0; i < n_in; i++) {
        if      (in_sizes[i] == BATCH * NIN)      X = (const float*)d_in[i];
        else if (in_sizes[i] == NIN * NOUT * NB)  C = (const float*)d_in[i];
        else if (in_sizes[i] == NIN * NOUT)       W = (const float*)d_in[i];
    }

    static bool attr_done = false;
    if (!attr_done) {
        cudaFuncSetAttribute(kan_gemm_i8,
                             cudaFuncAttributeMaxDynamicSharedMemorySize, SMEM_TOTAL);
        attr_done = true;
    }

    prep_a8<<<(BATCH * NIN / 4) / 256, 256>>>(X);
    prep_b8<<<(NIN * NOUT / 4) / 256, 256>>>(W, C);

    dim3 grid(BATCH / BM, NOUT / BN, SPLITK);   // (8, 4, 4) = 128 CTAs
    kan_gemm_i8<<<grid, 256, SMEM_TOTAL>>>((float*)d_out);
}

// round 10
// speedup vs baseline: 1.7782x; 1.7782x over previous
#include <cuda_runtime.h>
#include <cuda_bf16.h>
#include <math.h>
#include <stdint.h>

// ---------------------------------------------------------------------------
// KAN layer as one concatenated GEMM (mma.sync bf16 — fastest measured path;
// tcgen05 blocked by harness sm_103 target, legacy IMMA measured 2.5x slower).
// K layout (KTOT=7168): [0,512) silu_hi*w_hi, [512,1024) silu_lo*w_hi,
// [1024,1536) silu_hi*w_lo, [1536,7168): k=1536+kk*512+i spline*(w*c)
// GEMM schedule = round-2 measured-36us loop, verbatim. Fused deterministic
// split-K finalize replaces the separate reduce kernel.
// ---------------------------------------------------------------------------

#define BATCH 1024
#define NIN   512
#define NOUT  512
#define NB    11
#define KSIL  1536
#define KTOT  7168

#define BM 128
#define BN 128
#define BK 128
#define SPLITK 4
#define KSPLIT (KTOT / SPLITK)     // 1792
#define ITERS  (KSPLIT / BK)       // 14
#define STAGES 3
#define ASTAGE (BM * BK * 2)       // 32768
#define BSTAGE (BN * BK * 2)       // 32768
#define STAGE_BYTES (ASTAGE + BSTAGE)
#define SMEM_TOTAL (STAGES * STAGE_BYTES)   // 196608
#define SUBTILE 16384              // 128 rows x 64 cols bf16 (SW128 atom tile)

// Scratch (allocation-free rule: __device__ globals)
__device__ __align__(128) __nv_bfloat16 g_A [(size_t)BATCH * KTOT];
__device__ __align__(128) __nv_bfloat16 g_Bt[(size_t)NOUT  * KTOT];
__device__ __align__(128) float         g_P [(size_t)SPLITK * BATCH * NOUT];
__device__ int g_cnt[(BATCH / BM) * (NOUT / BN)];

// ---------------------------------------------------------------------------
// Cubic B-spline basis (Cox-de Boor recursion — measured faster than the
// closed-form select chain). knots t_m = -5.25 + 0.75*m (exact fp32)
// ---------------------------------------------------------------------------
__device__ __forceinline__ void basis11(float x, float* Bv /*[14]*/) {
#pragma unroll
    for (int m = 0; m < 14; m++) {
        float tl = -5.25f + 0.75f * (float)m;
        Bv[m] = (x >= tl && x < tl + 0.75f) ? 1.0f : 0.0f;
    }
#pragma unroll
    for (int d = 1; d <= 3; d++) {
        float inv = 1.0f / (0.75f * (float)d);
#pragma unroll
        for (int m = 0; m < 13; m++) {
            if (m < 14 - d) {
                float tm    = -5.25f + 0.75f * (float)m;
                float left  = (x - tm) * inv;
                float right = ((tm + 0.75f * (float)(d + 1)) - x) * inv;
                Bv[m] = left * Bv[m] + right * Bv[m + 1];
            }
        }
    }
}

__global__ void __launch_bounds__(256) prep_a_kernel(const float* __restrict__ X) {
    int pid = blockIdx.x * 256 + threadIdx.x;
    int b  = pid >> 8;
    int ip = (pid & 255) << 1;
    float2 xv = *(const float2*)(X + (size_t)b * NIN + ip);

    float s0 = xv.x / (1.0f + __expf(-xv.x));   // fast exp: rel err ~2^-21
    float s1 = xv.y / (1.0f + __expf(-xv.y));
    __nv_bfloat16 shi0 = __float2bfloat16(s0), shi1 = __float2bfloat16(s1);
    __nv_bfloat16 slo0 = __float2bfloat16(s0 - __bfloat162float(shi0));
    __nv_bfloat16 slo1 = __float2bfloat16(s1 - __bfloat162float(shi1));

    __nv_bfloat16* row = g_A + (size_t)b * KTOT;
    *(__nv_bfloat162*)(row + ip)        = __nv_bfloat162(shi0, shi1);
    *(__nv_bfloat162*)(row + 512 + ip)  = __nv_bfloat162(slo0, slo1);
    *(__nv_bfloat162*)(row + 1024 + ip) = __nv_bfloat162(shi0, shi1);

    float B0[14], B1[14];
    basis11(xv.x, B0);
    basis11(xv.y, B1);
#pragma unroll
    for (int kk = 0; kk < NB; kk++)
        *(__nv_bfloat162*)(row + KSIL + kk * NIN + ip) =
            __nv_bfloat162(__float2bfloat16(B0[kk]), __float2bfloat16(B1[kk]));
}

__global__ void __launch_bounds__(256) prep_b_kernel(const float* __restrict__ W,
                                                     const float* __restrict__ C) {
    int pid = blockIdx.x * 256 + threadIdx.x;
    int o  = pid >> 8;
    int ip = (pid & 255) << 1;

    float w0 = W[(size_t)ip * NOUT + o];
    float w1 = W[(size_t)(ip + 1) * NOUT + o];
    __nv_bfloat16 whi0 = __float2bfloat16(w0), whi1 = __float2bfloat16(w1);
    __nv_bfloat16 wlo0 = __float2bfloat16(w0 - __bfloat162float(whi0));
    __nv_bfloat16 wlo1 = __float2bfloat16(w1 - __bfloat162float(whi1));

    __nv_bfloat16* row = g_Bt + (size_t)o * KTOT;
    *(__nv_bfloat162*)(row + ip)        = __nv_bfloat162(whi0, whi1);
    *(__nv_bfloat162*)(row + 512 + ip)  = __nv_bfloat162(whi0, whi1);
    *(__nv_bfloat162*)(row + 1024 + ip) = __nv_bfloat162(wlo0, wlo1);

    const float* c0 = C + ((size_t)ip * NOUT + o) * NB;
    const float* c1 = C + ((size_t)(ip + 1) * NOUT + o) * NB;
#pragma unroll
    for (int kk = 0; kk < NB; kk++)
        *(__nv_bfloat162*)(row + KSIL + kk * NIN + ip) =
            __nv_bfloat162(__float2bfloat16(w0 * c0[kk]),
                           __float2bfloat16(w1 * c1[kk]));
}

// ---------------------------------------------------------------------------
// GEMM helpers
// ---------------------------------------------------------------------------
__device__ __forceinline__ void cpa16(uint32_t dst, const void* src) {
    asm volatile("cp.async.cg.shared.global [%0], [%1], 16;\n" :: "r"(dst), "l"(src));
}

#define LDSM_X4(r, addr)                                                       \
    asm volatile("ldmatrix.sync.aligned.m8n8.x4.shared.b16 {%0,%1,%2,%3}, [%4];\n" \
                 : "=r"((r)[0]), "=r"((r)[1]), "=r"((r)[2]), "=r"((r)[3])      \
                 : "r"(addr))

#define MMA16816(d, a, b0, b1)                                                 \
    asm volatile("mma.sync.aligned.m16n8k16.row.col.f32.bf16.bf16.f32 "        \
                 "{%0,%1,%2,%3}, {%4,%5,%6,%7}, {%8,%9}, {%0,%1,%2,%3};\n"     \
                 : "+f"((d)[0]), "+f"((d)[1]), "+f"((d)[2]), "+f"((d)[3])      \
                 : "r"((a)[0]), "r"((a)[1]), "r"((a)[2]), "r"((a)[3]),         \
                   "r"(b0), "r"(b1))

__device__ __forceinline__ void load_stage(const char* Ag, const char* Bg, int kt,
                                           int tid, uint32_t smem_u32) {
    uint32_t base = smem_u32 + (kt % STAGES) * STAGE_BYTES;
    const char* Ak = Ag + (size_t)kt * (BK * 2);
#pragma unroll
    for (int it = 0; it < 8; it++) {
        int t = tid + it * 256;
        int r = t >> 4, c = t & 15;
        uint32_t dst = base + ((c >> 3) << 14) + r * 128 + (((c & 7) ^ (r & 7)) << 4);
        cpa16(dst, Ak + (size_t)r * (KTOT * 2) + (c << 4));
    }
    const char* Bk = Bg + (size_t)kt * (BK * 2);
#pragma unroll
    for (int it = 0; it < 8; it++) {
        int t = tid + it * 256;
        int r = t >> 4, c = t & 15;
        uint32_t dst = base + ASTAGE + ((c >> 3) << 14) + r * 128 + (((c & 7) ^ (r & 7)) << 4);
        cpa16(dst, Bk + (size_t)r * (KTOT * 2) + (c << 4));
    }
    asm volatile("cp.async.commit_group;\n" ::);
}

__global__ void __launch_bounds__(256, 1) kan_gemm_kernel(float* __restrict__ Out) {
    extern __shared__ __align__(1024) char smem[];
    __shared__ int s_last;

    const uint32_t smem_u32 = (uint32_t)__cvta_generic_to_shared(smem);
    const int tid  = threadIdx.x;
    const int m0   = blockIdx.x * BM;
    const int n0   = blockIdx.y * BN;
    const int z    = blockIdx.z;

    const char* Ag = (const char*)g_A  + ((size_t)m0 * KTOT + (size_t)z * KSPLIT) * 2;
    const char* Bg = (const char*)g_Bt + ((size_t)n0 * KTOT + (size_t)z * KSPLIT) * 2;

    const int lane = tid & 31;
    const int warp = tid >> 5;
    const int wm   = warp >> 1;   // 0..3 : 32-row band
    const int wn   = warp & 1;    // 0..1 : 64-col band
    const int lr   = lane & 15;
    const int hf   = lane >> 4;

    float acc[2][8][4];
#pragma unroll
    for (int mt = 0; mt < 2; mt++)
#pragma unroll
        for (int nt = 0; nt < 8; nt++)
#pragma unroll
            for (int e = 0; e < 4; e++) acc[mt][nt][e] = 0.0f;

    // measured-36us schedule: 3 stages in flight, wait->sync->compute->sync->load
    load_stage(Ag, Bg, 0, tid, smem_u32);
    load_stage(Ag, Bg, 1, tid, smem_u32);
    load_stage(Ag, Bg, 2, tid, smem_u32);

    for (int kt = 0; kt < ITERS; kt++) {
        asm volatile("cp.async.wait_group 2;\n" ::);   // own stage-kt copies done
        __syncthreads();                               // all threads' copies visible

        const uint32_t sbase = smem_u32 + (kt % STAGES) * STAGE_BYTES;

#pragma unroll
        for (int ks = 0; ks < 8; ks++) {
            const int sub = ks >> 2;
            const int ck  = ks & 3;
            uint32_t af[2][4], bf[4][4];
#pragma unroll
            for (int mt = 0; mt < 2; mt++) {
                int r  = wm * 32 + mt * 16 + lr;
                int ch = (ck * 2 + hf) ^ (r & 7);
                LDSM_X4(af[mt], sbase + sub * SUBTILE + r * 128 + (ch << 4));
            }
#pragma unroll
            for (int p = 0; p < 4; p++) {
                int r  = wn * 64 + p * 16 + lr;
                int ch = (ck * 2 + hf) ^ (r & 7);
                LDSM_X4(bf[p], sbase + ASTAGE + sub * SUBTILE + r * 128 + (ch << 4));
            }
#pragma unroll
            for (int mt = 0; mt < 2; mt++)
#pragma unroll
                for (int p = 0; p < 4; p++)
#pragma unroll
                    for (int q = 0; q < 2; q++)
                        MMA16816(acc[mt][p * 2 + q], af[mt], bf[p][q], bf[p][q + 2]);
        }
        __syncthreads();                               // readers done with slot kt%3

        if (kt + STAGES < ITERS)
            load_stage(Ag, Bg, kt + STAGES, tid, smem_u32);
        else
            asm volatile("cp.async.commit_group;\n" ::);
    }

    // write split-K partial
    float* P = g_P + (size_t)z * BATCH * NOUT;
#pragma unroll
    for (int mt = 0; mt < 2; mt++)
#pragma unroll
        for (int nt = 0; nt < 8; nt++) {
            int row0 = m0 + wm * 32 + mt * 16 + (lane >> 2);
            int col  = n0 + wn * 64 + nt * 8 + (lane & 3) * 2;
            *(float2*)&P[(size_t)row0 * NOUT + col] =
                make_float2(acc[mt][nt][0], acc[mt][nt][1]);
            *(float2*)&P[(size_t)(row0 + 8) * NOUT + col] =
                make_float2(acc[mt][nt][2], acc[mt][nt][3]);
        }
    __threadfence();
    __syncthreads();

    // deterministic fixed-order finalization by last-arriving z for this tile
    const int tile = blockIdx.x * (NOUT / BN) + blockIdx.y;
    if (tid == 0) s_last = (atomicAdd(&g_cnt[tile], 1) == SPLITK - 1) ? 1 : 0;
    __syncthreads();
    if (s_last) {
        __threadfence();
        // 128 rows x 128 cols = 4096 float4, 256 threads -> 16 each
#pragma unroll
        for (int it = 0; it < 16; it++) {
            int t   = tid + it * 256;
            int row = m0 + (t >> 5);
            int c4  = (t & 31);
            size_t off = ((size_t)row * NOUT + n0) / 4 + c4;
            const float4* P0 = (const float4*)g_P + 0 * (size_t)(BATCH * NOUT / 4) + off;
            const float4* P1 = (const float4*)g_P + 1 * (size_t)(BATCH * NOUT / 4) + off;
            const float4* P2 = (const float4*)g_P + 2 * (size_t)(BATCH * NOUT / 4) + off;
            const float4* P3 = (const float4*)g_P + 3 * (size_t)(BATCH * NOUT / 4) + off;
            float4 a = *P0, b = *P1, c = *P2, e = *P3;
            float4 r;
            r.x = (a.x + b.x) + (c.x + e.x);
            r.y = (a.y + b.y) + (c.y + e.y);
            r.z = (a.z + b.z) + (c.z + e.z);
            r.w = (a.w + b.w) + (c.w + e.w);
            ((float4*)Out)[off] = r;
        }
        if (tid == 0) g_cnt[tile] = 0;   // rearm for graph replay
    }
}

// ---------------------------------------------------------------------------
extern "C" void kernel_launch(void* const* d_in, const int* in_sizes, int n_in,
                              void* d_out, int out_size) {
    const float* X = nullptr;
    const float* C = nullptr;
    const float* W = nullptr;
    for (int i = 0; i < n_in; i++) {
        if      (in_sizes[i] == BATCH * NIN)      X = (const float*)d_in[i];
        else if (in_sizes[i] == NIN * NOUT * NB)  C = (const float*)d_in[i];
        else if (in_sizes[i] == NIN * NOUT)       W = (const float*)d_in[i];
    }

    static bool attr_done = false;
    if (!attr_done) {
        cudaFuncSetAttribute(kan_gemm_kernel,
                             cudaFuncAttributeMaxDynamicSharedMemorySize, SMEM_TOTAL);
        attr_done = true;
    }

    prep_a_kernel<<<(BATCH * NIN / 2) / 256, 256>>>(X);
    prep_b_kernel<<<(NIN * NOUT / 2) / 256, 256>>>(W, C);

    dim3 grid(BATCH / BM, NOUT / BN, SPLITK);   // (8, 4, 4) = 128 CTAs
    kan_gemm_kernel<<<grid, 256, SMEM_TOTAL>>>((float*)d_out);
}

// round 11
// speedup vs baseline: 2.0715x; 1.1649x over previous
#include <cuda_runtime.h>
#include <cuda_bf16.h>
#include <math.h>
#include <stdint.h>

// ---------------------------------------------------------------------------
// KAN layer as one concatenated GEMM (mma.sync bf16 — fastest measured path).
// K layout (KTOT=7168): [0,512) silu_hi*w_hi, [512,1024) silu_lo*w_hi,
// [1024,1536) silu_hi*w_lo, [1536,7168): k=1536+kk*512+i spline*(w*c)
// GEMM = round-1 measured-36us kernel verbatim; SEPARATE reduce kernel
// (fused finalize measured +10us due to CTA-spread tail serialization).
// prep_a: closed-form cubic + smem scatter (replaces 190-op recursion).
// ---------------------------------------------------------------------------

#define BATCH 1024
#define NIN   512
#define NOUT  512
#define NB    11
#define KSIL  1536
#define KTOT  7168

#define BM 128
#define BN 128
#define BK 128
#define SPLITK 4
#define KSPLIT (KTOT / SPLITK)     // 1792
#define ITERS  (KSPLIT / BK)       // 14
#define STAGES 3
#define ASTAGE (BM * BK * 2)       // 32768
#define BSTAGE (BN * BK * 2)       // 32768
#define STAGE_BYTES (ASTAGE + BSTAGE)
#define SMEM_TOTAL (STAGES * STAGE_BYTES)   // 196608
#define SUBTILE 16384              // 128 rows x 64 cols bf16 (SW128 atom tile)

// Scratch (allocation-free rule: __device__ globals)
__device__ __align__(128) __nv_bfloat16 g_A [(size_t)BATCH * KTOT];
__device__ __align__(128) __nv_bfloat16 g_Bt[(size_t)NOUT  * KTOT];
__device__ __align__(128) float         g_P [(size_t)SPLITK * BATCH * NOUT];

// ---------------------------------------------------------------------------
// prep_a: silu hi/lo + closed-form uniform cubic B-spline via smem scatter.
// knots t_m = -5.25 + 0.75*m; cell jc = floor((x+5.25)/0.75), u = frac.
// nonzero weights (validated rel_err 9.1e-6 in earlier run):
//   m=jc-3: (1-u)^3/6   m=jc-2: (3u^3-6u^2+4)/6
//   m=jc-1: (-3u^3+3u^2+3u+1)/6   m=jc: u^3/6
// ---------------------------------------------------------------------------
__global__ void __launch_bounds__(256) prep_a_kernel(const float* __restrict__ X) {
    __shared__ uint32_t sc[256 * NB];          // per-thread 11-word scratch row
    const int tid = threadIdx.x;
    int pid = blockIdx.x * 256 + tid;
    int b  = pid >> 8;
    int ip = (pid & 255) << 1;
    float2 xv = *(const float2*)(X + (size_t)b * NIN + ip);

    float s0 = xv.x / (1.0f + __expf(-xv.x));
    float s1 = xv.y / (1.0f + __expf(-xv.y));
    __nv_bfloat16 shi0 = __float2bfloat16(s0), shi1 = __float2bfloat16(s1);
    __nv_bfloat16 slo0 = __float2bfloat16(s0 - __bfloat162float(shi0));
    __nv_bfloat16 slo1 = __float2bfloat16(s1 - __bfloat162float(shi1));

    __nv_bfloat16* row = g_A + (size_t)b * KTOT;
    *(__nv_bfloat162*)(row + ip)        = __nv_bfloat162(shi0, shi1);
    *(__nv_bfloat162*)(row + 512 + ip)  = __nv_bfloat162(slo0, slo1);
    *(__nv_bfloat162*)(row + 1024 + ip) = __nv_bfloat162(shi0, shi1);

    // zero this thread's scratch row (stride-11 words -> conflict-free)
#pragma unroll
    for (int kk = 0; kk < NB; kk++) sc[tid * NB + kk] = 0;

    unsigned short* sh = (unsigned short*)sc;
#pragma unroll
    for (int j = 0; j < 2; j++) {
        float x = j ? xv.y : xv.x;
        float pos = (x + 5.25f) * (1.0f / 0.75f);
        int jc = (int)floorf(pos);
        if (jc >= 0 && jc <= 13) {
            float u  = pos - (float)jc;
            float u2 = u * u, u3 = u2 * u;
            float omu = 1.0f - u;
            float w0 = omu * omu * omu * (1.0f / 6.0f);
            float w1 = (3.0f * u3 - 6.0f * u2 + 4.0f) * (1.0f / 6.0f);
            float w2 = (-3.0f * u3 + 3.0f * u2 + 3.0f * u + 1.0f) * (1.0f / 6.0f);
            float w3 = u3 * (1.0f / 6.0f);
#pragma unroll
            for (int d = 0; d < 4; d++) {
                int m = jc - 3 + d;
                if (m >= 0 && m <= 10) {
                    float wd = (d == 0) ? w0 : (d == 1) ? w1 : (d == 2) ? w2 : w3;
                    __nv_bfloat16 h = __float2bfloat16(wd);
                    sh[(tid * NB + m) * 2 + j] = *reinterpret_cast<unsigned short*>(&h);
                }
            }
        }
    }
    // per-thread scratch: no sync needed; copy 11 words coalesced to global
#pragma unroll
    for (int kk = 0; kk < NB; kk++)
        *(uint32_t*)(row + KSIL + kk * NIN + ip) = sc[tid * NB + kk];
}

__global__ void __launch_bounds__(256) prep_b_kernel(const float* __restrict__ W,
                                                     const float* __restrict__ C) {
    int pid = blockIdx.x * 256 + threadIdx.x;
    int o  = pid >> 8;
    int ip = (pid & 255) << 1;

    float w0 = W[(size_t)ip * NOUT + o];
    float w1 = W[(size_t)(ip + 1) * NOUT + o];
    __nv_bfloat16 whi0 = __float2bfloat16(w0), whi1 = __float2bfloat16(w1);
    __nv_bfloat16 wlo0 = __float2bfloat16(w0 - __bfloat162float(whi0));
    __nv_bfloat16 wlo1 = __float2bfloat16(w1 - __bfloat162float(whi1));

    __nv_bfloat16* row = g_Bt + (size_t)o * KTOT;
    *(__nv_bfloat162*)(row + ip)        = __nv_bfloat162(whi0, whi1);
    *(__nv_bfloat162*)(row + 512 + ip)  = __nv_bfloat162(whi0, whi1);
    *(__nv_bfloat162*)(row + 1024 + ip) = __nv_bfloat162(wlo0, wlo1);

    const float* c0 = C + ((size_t)ip * NOUT + o) * NB;
    const float* c1 = C + ((size_t)(ip + 1) * NOUT + o) * NB;
#pragma unroll
    for (int kk = 0; kk < NB; kk++)
        *(__nv_bfloat162*)(row + KSIL + kk * NIN + ip) =
            __nv_bfloat162(__float2bfloat16(w0 * c0[kk]),
                           __float2bfloat16(w1 * c1[kk]));
}

// ---------------------------------------------------------------------------
// GEMM helpers (round-1 measured-36us kernel, verbatim)
// ---------------------------------------------------------------------------
__device__ __forceinline__ void cpa16(uint32_t dst, const void* src) {
    asm volatile("cp.async.cg.shared.global [%0], [%1], 16;\n" :: "r"(dst), "l"(src));
}

#define LDSM_X4(r, addr)                                                       \
    asm volatile("ldmatrix.sync.aligned.m8n8.x4.shared.b16 {%0,%1,%2,%3}, [%4];\n" \
                 : "=r"((r)[0]), "=r"((r)[1]), "=r"((r)[2]), "=r"((r)[3])      \
                 : "r"(addr))

#define MMA16816(d, a, b0, b1)                                                 \
    asm volatile("mma.sync.aligned.m16n8k16.row.col.f32.bf16.bf16.f32 "        \
                 "{%0,%1,%2,%3}, {%4,%5,%6,%7}, {%8,%9}, {%0,%1,%2,%3};\n"     \
                 : "+f"((d)[0]), "+f"((d)[1]), "+f"((d)[2]), "+f"((d)[3])      \
                 : "r"((a)[0]), "r"((a)[1]), "r"((a)[2]), "r"((a)[3]),         \
                   "r"(b0), "r"(b1))

__device__ __forceinline__ void load_stage(const char* Ag, const char* Bg, int kt,
                                           int tid, uint32_t smem_u32) {
    uint32_t base = smem_u32 + (kt % STAGES) * STAGE_BYTES;
    const char* Ak = Ag + (size_t)kt * (BK * 2);
#pragma unroll
    for (int it = 0; it < 8; it++) {
        int t = tid + it * 256;
        int r = t >> 4, c = t & 15;
        uint32_t dst = base + ((c >> 3) << 14) + r * 128 + (((c & 7) ^ (r & 7)) << 4);
        cpa16(dst, Ak + (size_t)r * (KTOT * 2) + (c << 4));
    }
    const char* Bk = Bg + (size_t)kt * (BK * 2);
#pragma unroll
    for (int it = 0; it < 8; it++) {
        int t = tid + it * 256;
        int r = t >> 4, c = t & 15;
        uint32_t dst = base + ASTAGE + ((c >> 3) << 14) + r * 128 + (((c & 7) ^ (r & 7)) << 4);
        cpa16(dst, Bk + (size_t)r * (KTOT * 2) + (c << 4));
    }
    asm volatile("cp.async.commit_group;\n" ::);
}

__global__ void __launch_bounds__(256, 1) kan_gemm_kernel() {
    extern __shared__ __align__(1024) char smem[];
    const uint32_t smem_u32 = (uint32_t)__cvta_generic_to_shared(smem);
    const int tid  = threadIdx.x;
    const int m0   = blockIdx.x * BM;
    const int n0   = blockIdx.y * BN;
    const int z    = blockIdx.z;

    const char* Ag = (const char*)g_A  + ((size_t)m0 * KTOT + (size_t)z * KSPLIT) * 2;
    const char* Bg = (const char*)g_Bt + ((size_t)n0 * KTOT + (size_t)z * KSPLIT) * 2;

    const int lane = tid & 31;
    const int warp = tid >> 5;
    const int wm   = warp >> 1;   // 0..3 : 32-row band
    const int wn   = warp & 1;    // 0..1 : 64-col band
    const int lr   = lane & 15;
    const int hf   = lane >> 4;

    float acc[2][8][4];
#pragma unroll
    for (int mt = 0; mt < 2; mt++)
#pragma unroll
        for (int nt = 0; nt < 8; nt++)
#pragma unroll
            for (int e = 0; e < 4; e++) acc[mt][nt][e] = 0.0f;

    load_stage(Ag, Bg, 0, tid, smem_u32);
    load_stage(Ag, Bg, 1, tid, smem_u32);
    load_stage(Ag, Bg, 2, tid, smem_u32);

    for (int kt = 0; kt < ITERS; kt++) {
        asm volatile("cp.async.wait_group 2;\n" ::);
        __syncthreads();

        const uint32_t sbase = smem_u32 + (kt % STAGES) * STAGE_BYTES;

#pragma unroll
        for (int ks = 0; ks < 8; ks++) {
            const int sub = ks >> 2;
            const int ck  = ks & 3;
            uint32_t af[2][4], bf[4][4];
#pragma unroll
            for (int mt = 0; mt < 2; mt++) {
                int r  = wm * 32 + mt * 16 + lr;
                int ch = (ck * 2 + hf) ^ (r & 7);
                LDSM_X4(af[mt], sbase + sub * SUBTILE + r * 128 + (ch << 4));
            }
#pragma unroll
            for (int p = 0; p < 4; p++) {
                int r  = wn * 64 + p * 16 + lr;
                int ch = (ck * 2 + hf) ^ (r & 7);
                LDSM_X4(bf[p], sbase + ASTAGE + sub * SUBTILE + r * 128 + (ch << 4));
            }
#pragma unroll
            for (int mt = 0; mt < 2; mt++)
#pragma unroll
                for (int p = 0; p < 4; p++)
#pragma unroll
                    for (int q = 0; q < 2; q++)
                        MMA16816(acc[mt][p * 2 + q], af[mt], bf[p][q], bf[p][q + 2]);
        }
        __syncthreads();

        if (kt + STAGES < ITERS)
            load_stage(Ag, Bg, kt + STAGES, tid, smem_u32);
        else
            asm volatile("cp.async.commit_group;\n" ::);
    }

    // epilogue: split-K partials
    float* P = g_P + (size_t)z * BATCH * NOUT;
#pragma unroll
    for (int mt = 0; mt < 2; mt++)
#pragma unroll
        for (int nt = 0; nt < 8; nt++) {
            int row0 = m0 + wm * 32 + mt * 16 + (lane >> 2);
            int col  = n0 + wn * 64 + nt * 8 + (lane & 3) * 2;
            *(float2*)&P[(size_t)row0 * NOUT + col] =
                make_float2(acc[mt][nt][0], acc[mt][nt][1]);
            *(float2*)&P[(size_t)(row0 + 8) * NOUT + col] =
                make_float2(acc[mt][nt][2], acc[mt][nt][3]);
        }
}

// ---------------------------------------------------------------------------
// Deterministic fixed-order split-K reduction, MLP-16 (4 out-float4/thread)
// ---------------------------------------------------------------------------
__global__ void __launch_bounds__(256) reduce_kernel(float* __restrict__ Out) {
    const int t = blockIdx.x * 256 + threadIdx.x;     // 32768 threads
    const int Q = BATCH * NOUT / 4;                   // 131072 float4s
    const float4* P = (const float4*)g_P;
    float4 v[4][4];
#pragma unroll
    for (int r = 0; r < 4; r++) {
        int off = t + r * 32768;
#pragma unroll
        for (int z = 0; z < 4; z++)
            v[r][z] = P[(size_t)z * Q + off];
    }
#pragma unroll
    for (int r = 0; r < 4; r++) {
        float4 o;
        o.x = (v[r][0].x + v[r][1].x) + (v[r][2].x + v[r][3].x);
        o.y = (v[r][0].y + v[r][1].y) + (v[r][2].y + v[r][3].y);
        o.z = (v[r][0].z + v[r][1].z) + (v[r][2].z + v[r][3].z);
        o.w = (v[r][0].w + v[r][1].w) + (v[r][2].w + v[r][3].w);
        ((float4*)Out)[t + r * 32768] = o;
    }
}

// ---------------------------------------------------------------------------
extern "C" void kernel_launch(void* const* d_in, const int* in_sizes, int n_in,
                              void* d_out, int out_size) {
    const float* X = nullptr;
    const float* C = nullptr;
    const float* W = nullptr;
    for (int i = 0; i < n_in; i++) {
        if      (in_sizes[i] == BATCH * NIN)      X = (const float*)d_in[i];
        else if (in_sizes[i] == NIN * NOUT * NB)  C = (const float*)d_in[i];
        else if (in_sizes[i] == NIN * NOUT)       W = (const float*)d_in[i];
    }

    static bool attr_done = false;
    if (!attr_done) {
        cudaFuncSetAttribute(kan_gemm_kernel,
                             cudaFuncAttributeMaxDynamicSharedMemorySize, SMEM_TOTAL);
        attr_done = true;
    }

    prep_a_kernel<<<(BATCH * NIN / 2) / 256, 256>>>(X);
    prep_b_kernel<<<(NIN * NOUT / 2) / 256, 256>>>(W, C);

    dim3 grid(BATCH / BM, NOUT / BN, SPLITK);   // (8, 4, 4) = 128 CTAs
    kan_gemm_kernel<<<grid, 256, SMEM_TOTAL>>>();

    reduce_kernel<<<128, 256>>>((float*)d_out);
}